// round 7
// baseline (speedup 1.0000x reference)
#include <cuda_runtime.h>
#include <cuda_fp16.h>
#include <cstdint>

typedef unsigned long long u64;
typedef unsigned int u32;

#define NCONV 8
#define HO    62
#define WO    62

__device__ __forceinline__ u32 smem_u32(const void* p) {
    u32 a;
    asm("{ .reg .u64 t; cvta.to.shared.u64 t, %1; cvt.u32.u64 %0, t; }" : "=r"(a) : "l"(p));
    return a;
}
__device__ __forceinline__ void fma2(u64 &d, u64 a, u64 b) {
    asm("fma.rn.f32x2 %0, %1, %2, %0;" : "+l"(d) : "l"(a), "l"(b));
}
__device__ __forceinline__ u64 dup2(float v) {
    u64 r; asm("mov.b64 %0, {%1, %1};" : "=l"(r) : "f"(v)); return r;
}
__device__ __forceinline__ float lo32(u64 a) { return __uint_as_float((u32)(a & 0xFFFFFFFFULL)); }
__device__ __forceinline__ float hi32(u64 a) { return __uint_as_float((u32)(a >> 32)); }
__device__ __forceinline__ u32 pack_h2(float lo, float hi) {
    u32 r; asm("cvt.rn.f16x2.f32 %0, %1, %2;" : "=r"(r) : "f"(hi), "f"(lo)); return r;
}

__device__ __forceinline__ void ldsm_x2(u32 &r0, u32 &r1, u32 addr) {
    asm volatile("ldmatrix.sync.aligned.m8n8.x2.shared.b16 {%0,%1}, [%2];"
                 : "=r"(r0), "=r"(r1) : "r"(addr));
}
__device__ __forceinline__ u32 ldsm_x1(u32 addr) {
    u32 r;
    asm volatile("ldmatrix.sync.aligned.m8n8.x1.shared.b16 {%0}, [%1];"
                 : "=r"(r) : "r"(addr));
    return r;
}
__device__ __forceinline__ void mma_16n8k8(float c[4], u32 a0, u32 a1, u32 b) {
    asm volatile(
        "mma.sync.aligned.m16n8k8.row.col.f32.f16.f16.f32 "
        "{%0,%1,%2,%3}, {%4,%5}, {%6}, {%0,%1,%2,%3};"
        : "+f"(c[0]), "+f"(c[1]), "+f"(c[2]), "+f"(c[3])
        : "r"(a0), "r"(a1), "r"(b));
}

__global__ __launch_bounds__(128, 8)
void kan_hmma_kernel(const float* __restrict__ x,
                     const float* __restrict__ base_w,
                     const float* __restrict__ spline_w,
                     const float* __restrict__ spline_s,
                     const float* __restrict__ grid,
                     float* __restrict__ out) {
    // feature plane: 4 input rows x 64 cols x 8 fp16 basis (16B per pixel)
    __shared__ __align__(16) uint4  s_feat[4 * 64];           // 4096 B
    __shared__ float                s_silu[4 * 64];           // 1024 B
    __shared__ __align__(16) __half s_btap[9 * 8 * 8];        // 1152 B  [tap][n][s]
    __shared__ __align__(16) u64    s_wb[9 * 4];              // 288 B   [tap][npair]

    const int tid  = threadIdx.x;
    const int w    = tid >> 5;
    const int lane = tid & 31;
    const int band = blockIdx.x;          // 0..7
    const int img  = blockIdx.y;          // 0..255

    // ---- Phase 0: weight staging ----
    // B taps: btap[tap][n][s] = spline_w[n][tap][s] * spline_s[n][tap]  (fp16)
    for (int idx = tid; idx < 9 * 64; idx += 128) {
        int tap = idx >> 6, r = idx & 63, n = r >> 3, s = r & 7;
        float v = spline_w[(n * 9 + tap) * NCONV + s] * spline_s[n * 9 + tap];
        s_btap[idx] = __float2half_rn(v);
    }
    // base weights packed over n-pairs
    if (tid < 36) {
        int tap = tid >> 2, q = tid & 3;
        float a = base_w[(2 * q) * 9 + tap];
        float b = base_w[(2 * q + 1) * 9 + tap];
        u64 pr; asm("mov.b64 %0, {%1, %2};" : "=l"(pr) : "f"(a), "f"(b));
        s_wb[tid] = pr;
    }
    const float g0    = grid[0];
    const float inv_h = 1.0f / (grid[1] - grid[0]);
    __syncthreads();

    // ---- hoist B fragments (once per kernel): b[tap] for m16n8k8 ----
    // btap row n = 8 halves along k; ldmatrix row addr = &btap[tap][lane&7][0]
    u32 bfrag[9];
    const u32 btap_base = smem_u32(s_btap);
    #pragma unroll
    for (int tap = 0; tap < 9; ++tap)
        bfrag[tap] = ldsm_x1(btap_base + (tap * 8 + (lane & 7)) * 16);

    // hoist base-weight pairs for this thread's n-pair (q = lane&3)
    u64 wbr[9];
    #pragma unroll
    for (int tap = 0; tap < 9; ++tap)
        wbr[tap] = s_wb[tap * 4 + (lane & 3)];

    const float* xin = x + img * 4096;
    const u32 feat_base = smem_u32(s_feat);
    const int ntiles = min(4, 31 - band * 4);

    for (int t = 0; t < ntiles; ++t) {
        const int yt0 = (band * 4 + t) * 2;   // first output row of this tile

        __syncthreads();   // previous tile fully consumed

        // ---- A-build: silu plane (fp32) + basis plane (8 x fp16 per pixel) ----
        #pragma unroll
        for (int e = tid; e < 256; e += 128) {
            int row = e >> 6, col = e & 63;
            float v = xin[(yt0 + row) * 64 + col];

            float sig = 1.0f / (1.0f + __expf(-v));
            s_silu[e] = v * sig;

            float u  = (v - g0) * inv_h;
            float fj = floorf(u);
            int   j0 = (int)fj;
            float tt = u - fj;
            float t2 = tt * tt, t3 = t2 * tt, om = 1.0f - tt;
            const float s6 = 1.0f / 6.0f;
            float c0 = om * om * om * s6;
            float c1 = (3.0f * t3 - 6.0f * t2 + 4.0f) * s6;
            float c2 = (-3.0f * t3 + 3.0f * t2 + 3.0f * tt + 1.0f) * s6;
            float c3 = t3 * s6;

            int jb = j0 - 3;   // basis index holding c0
            u32 hh[4];
            #pragma unroll
            for (int i = 0; i < 4; ++i) {
                int da = 2 * i - jb, db = 2 * i + 1 - jb;
                float ha = (da == 0) ? c0 : (da == 1) ? c1 : (da == 2) ? c2 : (da == 3) ? c3 : 0.0f;
                float hb = (db == 0) ? c0 : (db == 1) ? c1 : (db == 2) ? c2 : (db == 3) ? c3 : 0.0f;
                hh[i] = pack_h2(ha, hb);
            }
            s_feat[e] = make_uint4(hh[0], hh[1], hh[2], hh[3]);
        }
        __syncthreads();

        // ---- tensor phase: 2 m16-tiles per warp, 9 taps of m16n8k8 ----
        // per-lane A base address (pixel for ldmatrix row l = m0 + (lane&15))
        u32 abase[2];
        #pragma unroll
        for (int tau = 0; tau < 2; ++tau) {
            int m = w * 32 + tau * 16 + (lane & 15);
            int rt = (m >= WO) ? 1 : 0;
            int xx = m - rt * WO;
            if (m >= 2 * WO) { rt = 0; xx = 0; }   // pad rows -> dummy addr
            abase[tau] = feat_base + (rt * 64 + xx) * 16;
        }

        float c[2][4];
        #pragma unroll
        for (int tau = 0; tau < 2; ++tau)
            #pragma unroll
            for (int i = 0; i < 4; ++i) c[tau][i] = 0.0f;

        #pragma unroll
        for (int tap = 0; tap < 9; ++tap) {
            const int dy = tap / 3, dx = tap % 3;
            const u32 off = (u32)(dy * 64 + dx) * 16;
            u32 a0, a1;
            ldsm_x2(a0, a1, abase[0] + off);
            mma_16n8k8(c[0], a0, a1, bfrag[tap]);
            ldsm_x2(a0, a1, abase[1] + off);
            mma_16n8k8(c[1], a0, a1, bfrag[tap]);
        }

        // ---- epilogue: add fp32 base (silu) term, store ----
        // c-frag: rows t/4 (+8), cols n0=(lane&3)*2, n0+1
        const int n0 = (lane & 3) * 2;
        #pragma unroll
        for (int tau = 0; tau < 2; ++tau) {
            #pragma unroll
            for (int g = 0; g < 2; ++g) {
                int m = w * 32 + tau * 16 + g * 8 + (lane >> 2);
                if (m < 2 * WO) {
                    int rt = (m >= WO) ? 1 : 0;
                    int xx = m - rt * WO;

                    u64 bacc = 0ULL;
                    #pragma unroll
                    for (int tap = 0; tap < 9; ++tap) {
                        const int dy = tap / 3, dx = tap % 3;
                        float s = s_silu[(rt + dy) * 64 + xx + dx];
                        fma2(bacc, dup2(s), wbr[tap]);
                    }

                    int y = yt0 + rt;
                    float* po = out + ((img * NCONV + n0) * HO + y) * WO + xx;
                    po[0]       = c[tau][g * 2 + 0] + lo32(bacc);
                    po[HO * WO] = c[tau][g * 2 + 1] + hi32(bacc);
                }
            }
        }
    }
}

extern "C" void kernel_launch(void* const* d_in, const int* in_sizes, int n_in,
                              void* d_out, int out_size) {
    const float* x  = (const float*)d_in[0];
    const float* bw = (const float*)d_in[1];
    const float* sw = (const float*)d_in[2];
    const float* ss = (const float*)d_in[3];
    const float* gr = (const float*)d_in[4];
    float* out = (float*)d_out;

    dim3 grd(8, 256);   // 8 bands (of four 2-row tiles) x 256 images
    kan_hmma_kernel<<<grd, 128>>>(x, bw, sw, ss, gr, out);
}